// round 14
// baseline (speedup 1.0000x reference)
#include <cuda_runtime.h>
#include <math.h>
#include <stdint.h>

#define DD 1024
#define BB 32
#define SS 512
#define NC 8             // columns per block
#define NBLK 128         // 128*8 = 1024 columns
#define NTHR 256
#define WU_STRIDE 2052   // 1024*2 + 4 pad (floats)
#define H_STRIDE 1028    // 1024 + 4 pad (floats)

__device__ float g_h0all[(size_t)SS * BB * DD];  // layer-0 out, [S][B][D]
__device__ float g_h[2][BB * DD];                // recurrent state, [B][D]
__device__ unsigned g_done[2];

// ---- lockstep sync (validated) ----
__device__ __forceinline__ unsigned ld_acq(const unsigned* p) {
    unsigned v;
    asm volatile("ld.acquire.gpu.global.u32 %0, [%1];" : "=r"(v) : "l"(p) : "memory");
    return v;
}
__device__ __forceinline__ void red_release_add(unsigned* p) {
    asm volatile("red.release.gpu.global.add.u32 [%0], %1;" :: "l"(p), "r"(1u) : "memory");
}
__device__ __forceinline__ void wait_ge(const unsigned* ctr, unsigned target) {
    if (threadIdx.x == 0) { while (ld_acq(ctr) < target) { } }
    __syncthreads();
}

// ---- packed f32x2 helpers (each half = independently rounded fp32 fma -> bit-exact) ----
__device__ __forceinline__ void fma2(unsigned long long& acc, unsigned long long a,
                                     unsigned long long b) {
    asm("fma.rn.f32x2 %0, %1, %2, %0;" : "+l"(acc) : "l"(a), "l"(b));
}
__device__ __forceinline__ unsigned long long pack2(float lo, float hi) {
    unsigned long long d;
    asm("mov.b64 %0, {%1, %2};" : "=l"(d) : "f"(lo), "f"(hi));
    return d;
}
__device__ __forceinline__ void unpack2(float& lo, float& hi, unsigned long long v) {
    asm("mov.b64 {%0, %1}, %2;" : "=f"(lo), "=f"(hi) : "l"(v));
}

// ---- XLA EmitFastTanh (with_fma): clamp 7.99881172180175781, fma Horner ----
__device__ __forceinline__ float xla_tanh_fma(float x) {
    const float kMax = 7.99881172180175781f;
    float tc = fmaxf(fminf(x, kMax), -kMax);
    float x2 = __fmul_rn(tc, tc);
    float p;
    p = fmaf(x2, -2.76076847742355e-16f, 2.00018790482477e-13f);
    p = fmaf(x2, p, -8.60467152213735e-11f);
    p = fmaf(x2, p,  5.12229709037114e-08f);
    p = fmaf(x2, p,  1.48572235717979e-05f);
    p = fmaf(x2, p,  6.37261928875436e-04f);
    p = fmaf(x2, p,  4.89352455891786e-03f);
    p = __fmul_rn(tc, p);
    float q;
    q = fmaf(x2, 1.19825839466702e-06f, 1.18534705686654e-04f);
    q = fmaf(x2, q, 2.26843463243900e-03f);
    q = fmaf(x2, q, 4.89352518554385e-03f);
    float r = __fdiv_rn(p, q);
    return (fabsf(x) < 0.0004f) ? x : r;
}

__global__ void init_kernel() { g_done[0] = 0u; g_done[1] = 0u; }

// One layer, 512 lockstep steps. Per output (b,n):
//   ax = [seq fma chain k=0..511] +rn [seq fma chain k=512..1023]  (x-side)
//   ah = same over h; pre = (ax +rn ah) +rn bias; out = XLA fma-tanh.
// Halves live in different threads (kh); x/h FMAs packed as f32x2 lo/hi.
__global__ void __launch_bounds__(NTHR, 1) rnn_layer(
    const float* __restrict__ in, size_t in_st_t, size_t in_st_b,  // in[t*st_t+b*st_b+k]
    const float* __restrict__ W,      // [D][D] k-major
    const float* __restrict__ U,
    const float* __restrict__ bias_l, // [D]
    float* __restrict__ outp, size_t out_st_t, size_t out_st_b,
    int ctr_idx)
{
    extern __shared__ float smem[];
    float*  wu   = smem;                               // [8][WU_STRIDE]  {W,U} interleaved
    float*  hsh  = smem + NC * WU_STRIDE;              // [32][H_STRIDE]  staged h_{t-1}
    float4* red4 = (float4*)(hsh + BB * H_STRIDE);     // [2][32][4]

    const int nb  = blockIdx.x * NC;
    const int tid = threadIdx.x;
    unsigned* ctr = &g_done[ctr_idx];

    // build interleaved weights (once): wu[c][2k]=W[k][nb+c], wu[c][2k+1]=U[k][nb+c]
    for (int i = tid; i < NC * DD; i += NTHR) {
        int c = i >> 10, k = i & 1023;
        wu[c * WU_STRIDE + 2 * k]     = W[(size_t)k * DD + nb + c];
        wu[c * WU_STRIDE + 2 * k + 1] = U[(size_t)k * DD + nb + c];
    }
    // h_{-1} = 0 in slot 1 (step 0 reads slot (0+1)&1)
    if (tid < 128) {
        int b = tid >> 2, cp = tid & 3;
        *(float2*)&g_h[1][b * DD + nb + cp * 2] = make_float2(0.f, 0.f);
    }
    __threadfence();
    __syncthreads();
    if (tid == 0) red_release_add(ctr);

    // roles
    const int w    = tid >> 5;
    const int lane = tid & 31;
    const int bq   = w & 3;          // batch quarter
    const int kh   = w >> 2;         // k-half 0/1
    const int bsub = lane & 7;
    const int cp   = lane >> 3;      // column pair 0..3
    const int b    = bq * 8 + bsub;
    const int c0   = cp * 2;
    const float bv0 = bias_l[nb + (tid & 3) * 2];
    const float bv1 = bias_l[nb + (tid & 3) * 2 + 1];

    const float* hsrc[2] = { g_h[0], g_h[1] };
    const unsigned long long* w0base = (const unsigned long long*)(wu + c0 * WU_STRIDE + kh * 1024);
    const unsigned long long* w1base = (const unsigned long long*)(wu + (c0 + 1) * WU_STRIDE + kh * 1024);

    for (int t = 0; t < SS; ++t) {
        wait_ge(ctr, (unsigned)NBLK * (unsigned)(t + 1));

        // ---- stage h_{t-1} -> smem (coalesced, no sector waste) ----
        {
            const float* hs = hsrc[(t + 1) & 1];
            for (int i = tid; i < BB * (DD / 4); i += NTHR) {
                int bb = i >> 8, q = i & 255;
                float4 hv = __ldcg((const float4*)(hs + (size_t)bb * DD) + q);
                *(float4*)(hsh + bb * H_STRIDE + q * 4) = hv;
            }
        }
        __syncthreads();

        // ---- packed chains over my k-half (ascending k, strictly sequential) ----
        const float4* xp = (const float4*)(in + (size_t)t * in_st_t + (size_t)b * in_st_b + kh * 512);
        const float4* hp = (const float4*)(hsh + b * H_STRIDE + kh * 512);

        unsigned long long acc0 = 0ull, acc1 = 0ull;
#pragma unroll 4
        for (int q = 0; q < 128; ++q) {
            const float4 xv = __ldg(xp + q);
            const float4 hv = hp[q];
            const unsigned long long a0 = pack2(xv.x, hv.x);
            const unsigned long long a1 = pack2(xv.y, hv.y);
            const unsigned long long a2 = pack2(xv.z, hv.z);
            const unsigned long long a3 = pack2(xv.w, hv.w);
            const ulonglong2 wA = ((const ulonglong2*)w0base)[2 * q];
            const ulonglong2 wB = ((const ulonglong2*)w0base)[2 * q + 1];
            const ulonglong2 wC = ((const ulonglong2*)w1base)[2 * q];
            const ulonglong2 wD = ((const ulonglong2*)w1base)[2 * q + 1];
            fma2(acc0, a0, wA.x);
            fma2(acc1, a0, wC.x);
            fma2(acc0, a1, wA.y);
            fma2(acc1, a1, wC.y);
            fma2(acc0, a2, wB.x);
            fma2(acc1, a2, wD.x);
            fma2(acc0, a3, wB.y);
            fma2(acc1, a3, wD.y);
        }

        // ---- exchange halves ----
        float ax0, ah0, ax1, ah1;
        unpack2(ax0, ah0, acc0);
        unpack2(ax1, ah1, acc1);
        red4[kh * 128 + b * 4 + cp] = make_float4(ax0, ah0, ax1, ah1);
        __syncthreads();

        // ---- join halves, bias, tanh, publish (128 threads, 2 outputs each) ----
        if (tid < 128) {
            const int b2 = tid >> 2, cp2 = tid & 3;
            const float4 f0 = red4[b2 * 4 + cp2];
            const float4 f1 = red4[128 + b2 * 4 + cp2];
            const float axA = __fadd_rn(f0.x, f1.x);
            const float ahA = __fadd_rn(f0.y, f1.y);
            const float v0  = xla_tanh_fma(__fadd_rn(__fadd_rn(axA, ahA), bv0));
            const float axB = __fadd_rn(f0.z, f1.z);
            const float ahB = __fadd_rn(f0.w, f1.w);
            const float v1  = xla_tanh_fma(__fadd_rn(__fadd_rn(axB, ahB), bv1));
            *(float2*)&g_h[t & 1][b2 * DD + nb + cp2 * 2] = make_float2(v0, v1);
            *(float2*)(outp + (size_t)t * out_st_t + (size_t)b2 * out_st_b + nb + cp2 * 2)
                = make_float2(v0, v1);
        }
        __threadfence();
        __syncthreads();
        if (tid == 0) red_release_add(ctr);
        __syncthreads();   // protect red4/hsh from next-iter overwrite
    }
}

extern "C" void kernel_launch(void* const* d_in, const int* in_sizes, int n_in,
                              void* d_out, int out_size) {
    const float* x    = (const float*)d_in[0];   // [32,512,1024]
    const float* wh   = (const float*)d_in[1];   // [2,1024,1024]
    const float* uh   = (const float*)d_in[2];   // [2,1024,1024]
    const float* bias = (const float*)d_in[3];   // [2,1024]
    float* out = (float*)d_out;                  // [32,512,1024]

    const int smem_bytes = (NC * WU_STRIDE + BB * H_STRIDE) * (int)sizeof(float)
                         + 2 * 32 * 4 * (int)sizeof(float4);   // 65664+131584+4096=201344
    cudaFuncSetAttribute(rnn_layer, cudaFuncAttributeMaxDynamicSharedMemorySize, smem_bytes);

    float* h0all; cudaGetSymbolAddress((void**)&h0all, g_h0all);

    init_kernel<<<1, 1>>>();
    // layer 0: x native [B][S][D] -> h0all [S][B][D]
    rnn_layer<<<NBLK, NTHR, smem_bytes>>>(
        x, (size_t)DD, (size_t)SS * DD,
        wh, uh, bias,
        h0all, (size_t)BB * DD, (size_t)DD, 0);
    // layer 1: h0all [S][B][D] -> out native [B][S][D]
    rnn_layer<<<NBLK, NTHR, smem_bytes>>>(
        h0all, (size_t)BB * DD, (size_t)DD,
        wh + DD * DD, uh + DD * DD, bias + DD,
        out, (size_t)DD, (size_t)SS * DD, 1);
}

// round 16
// speedup vs baseline: 1.7702x; 1.7702x over previous
#include <cuda_runtime.h>
#include <math.h>
#include <stdint.h>

#define DD 1024
#define BB 32
#define SS 512
#define NC 8             // columns per block
#define NBLK 128
#define NTHR 256         // 8 warps = 4 col-pairs x 2 k-halves
#define QSTR 258         // quarter-panel row stride (float2)
#define WUSTR 1026       // weight row stride (float2)

__device__ float g_h0all[(size_t)SS * BB * DD];  // layer-0 out, [S][B][D]
__device__ float g_h[2][BB * DD];                // recurrent state, [B][D]
__device__ unsigned g_done[2];

// ---- lockstep sync (validated) ----
__device__ __forceinline__ unsigned ld_acq(const unsigned* p) {
    unsigned v;
    asm volatile("ld.acquire.gpu.global.u32 %0, [%1];" : "=r"(v) : "l"(p) : "memory");
    return v;
}
__device__ __forceinline__ void red_release_add(unsigned* p) {
    asm volatile("red.release.gpu.global.add.u32 [%0], %1;" :: "l"(p), "r"(1u) : "memory");
}
__device__ __forceinline__ void wait_ge(const unsigned* ctr, unsigned target) {
    if (threadIdx.x == 0) { while (ld_acq(ctr) < target) { } }
    __syncthreads();
}

// ---- f32x2 (lo/hi = independently-rounded fp32 fma; bit-exact, validated R14) ----
__device__ __forceinline__ void fma2(unsigned long long& acc, unsigned long long a,
                                     unsigned long long b) {
    asm("fma.rn.f32x2 %0, %1, %2, %0;" : "+l"(acc) : "l"(a), "l"(b));
}

// ---- XLA EmitFastTanh (with_fma): clamp 7.99881172180175781, fma Horner ----
__device__ __forceinline__ float xla_tanh_fma(float x) {
    const float kMax = 7.99881172180175781f;
    float tc = fmaxf(fminf(x, kMax), -kMax);
    float x2 = __fmul_rn(tc, tc);
    float p;
    p = fmaf(x2, -2.76076847742355e-16f, 2.00018790482477e-13f);
    p = fmaf(x2, p, -8.60467152213735e-11f);
    p = fmaf(x2, p,  5.12229709037114e-08f);
    p = fmaf(x2, p,  1.48572235717979e-05f);
    p = fmaf(x2, p,  6.37261928875436e-04f);
    p = fmaf(x2, p,  4.89352455891786e-03f);
    p = __fmul_rn(tc, p);
    float q;
    q = fmaf(x2, 1.19825839466702e-06f, 1.18534705686654e-04f);
    q = fmaf(x2, q, 2.26843463243900e-03f);
    q = fmaf(x2, q, 4.89352518554385e-03f);
    float r = __fdiv_rn(p, q);
    return (fabsf(x) < 0.0004f) ? x : r;
}

__global__ void init_kernel() { g_done[0] = 0u; g_done[1] = 0u; }
__global__ void nop_kernel() {}

// One layer, 512 lockstep steps.
// Warp w: col-pair cp=w>>1 (local cols 2cp, 2cp+1), k-half kh=w&1.
// Each warp's 512-k chain = 2 contiguous 256-k phases with carried accumulator
// (ONE sequential ascending-k chain). kc=512 join = single __fadd_rn at publish.
__global__ void __launch_bounds__(NTHR, 1) rnn_layer(
    const float* __restrict__ in, size_t in_st_t, size_t in_st_b,  // in[t*st_t+b*st_b+k]
    const float* __restrict__ W,      // [D][D] k-major
    const float* __restrict__ U,
    const float* __restrict__ bias_l, // [D]
    float* __restrict__ outp, size_t out_st_t, size_t out_st_b,
    int ctr_idx)
{
    extern __shared__ float smem[];
    float2* wu2  = (float2*)smem;                        // [8][WUSTR] (W,U) per k
    float2* q0   = wu2 + NC * WUSTR;                     // [32][QSTR] kh=0 quarter
    float2* q1   = q0 + BB * QSTR;                       // [32][QSTR] kh=1 quarter
    float2* red2 = q1 + BB * QSTR;                       // [2*8][33]

    const int nb  = blockIdx.x * NC;
    const int tid = threadIdx.x;
    unsigned* ctr = &g_done[ctr_idx];

    // interleaved weights (once): wu2[c][k] = (W[k][nb+c], U[k][nb+c])
    for (int i = tid; i < NC * DD; i += NTHR) {
        int c = i >> 10, k = i & 1023;
        wu2[c * WUSTR + k] = make_float2(W[(size_t)k * DD + nb + c],
                                         U[(size_t)k * DD + nb + c]);
    }
    // h_{-1} = 0 in slot 1 (step 0 reads slot (0+1)&1)
    {
        int b = tid & 31, c = tid >> 5;
        g_h[1][b * DD + nb + c] = 0.f;
    }
    __syncthreads();
    if (tid == 0) red_release_add(ctr);   // release orders the zero-stores

    const int w    = tid >> 5;
    const int lane = tid & 31;            // = batch b for compute
    const int cp   = w >> 1;
    const int kh   = w & 1;
    const int l0   = 2 * cp, l1 = 2 * cp + 1;
    const float bv = bias_l[nb + (tid >> 5)];   // publish role: col = tid>>5

    const float2* myq  = (kh ? q1 : q0) + lane * QSTR;
    const float2* wu_a = wu2 + l0 * WUSTR + kh * 512;
    const float2* wu_b = wu2 + l1 * WUSTR + kh * 512;

    for (int t = 0; t < SS; ++t) {
        wait_ge(ctr, (unsigned)NBLK * (unsigned)(t + 1));

        const float* xin = in + (size_t)t * in_st_t;
        const float* hin = g_h[(t + 1) & 1];

        unsigned long long acc0 = 0ull, acc1 = 0ull;   // (ax,ah) for cols l0, l1
#pragma unroll
        for (int p = 0; p < 2; ++p) {
            // ---- stage quarters at panel offset 0: q0: k in [p*256,+256); q1: +512 ----
            for (int i = tid; i < 4096; i += NTHR) {
                int qq = i >> 11, b = (i >> 6) & 31, g = i & 63;
                int koff = qq * 512 + p * 256 + 4 * g;
                float4 xv = __ldg((const float4*)(xin + (size_t)b * in_st_b + koff));
                float4 hv = __ldcg((const float4*)(hin + (size_t)b * DD + koff));
                float2* dst = (qq ? q1 : q0) + b * QSTR + 4 * g;
                *(float4*)(dst)     = make_float4(xv.x, hv.x, xv.y, hv.y);
                *(float4*)(dst + 2) = make_float4(xv.z, hv.z, xv.w, hv.w);
            }
            __syncthreads();

            // ---- chains over my 256-k chunk (ascending k, acc carried across phases) ----
            const ulonglong2* xh = (const ulonglong2*)(myq);            // FIXED: offset 0
            const ulonglong2* wa = (const ulonglong2*)(wu_a + p * 256); // weights advance
            const ulonglong2* wb = (const ulonglong2*)(wu_b + p * 256);
#pragma unroll 4
            for (int j = 0; j < 128; ++j) {
                const ulonglong2 a = xh[j];
                const ulonglong2 u = wa[j];
                const ulonglong2 v = wb[j];
                fma2(acc0, a.x, u.x);
                fma2(acc1, a.x, v.x);
                fma2(acc0, a.y, u.y);
                fma2(acc1, a.y, v.y);
            }
            __syncthreads();   // quarter consumed before next staging
        }

        // ---- exchange halves: red2[kh*8 + col][b] = (ax_half, ah_half) ----
        *(unsigned long long*)&red2[(kh * 8 + l0) * 33 + lane] = acc0;
        *(unsigned long long*)&red2[(kh * 8 + l1) * 33 + lane] = acc1;
        __syncthreads();

        // ---- join (kc=512), bias, tanh, publish: thread -> (b2, c2) ----
        {
            const int b2 = tid & 31, c2 = tid >> 5;
            const float2 f0 = red2[c2 * 33 + b2];          // kh=0 (k < 512)  first
            const float2 f1 = red2[(8 + c2) * 33 + b2];    // kh=1 (k >= 512) second
            const float ax = __fadd_rn(f0.x, f1.x);
            const float ah = __fadd_rn(f0.y, f1.y);
            const float v  = xla_tanh_fma(__fadd_rn(__fadd_rn(ax, ah), bv));
            g_h[t & 1][b2 * DD + nb + c2] = v;
            outp[(size_t)t * out_st_t + (size_t)b2 * out_st_b + nb + c2] = v;
        }
        __syncthreads();
        if (tid == 0) red_release_add(ctr);   // release orders h/out stores
        // no tail sync needed: red2 rewritten only after 2 barriers next iter
    }
}

extern "C" void kernel_launch(void* const* d_in, const int* in_sizes, int n_in,
                              void* d_out, int out_size) {
    const float* x    = (const float*)d_in[0];   // [32,512,1024]
    const float* wh   = (const float*)d_in[1];   // [2,1024,1024]
    const float* uh   = (const float*)d_in[2];   // [2,1024,1024]
    const float* bias = (const float*)d_in[3];   // [2,1024]
    float* out = (float*)d_out;                  // [32,512,1024]

    const int smem_bytes = (NC * WUSTR + 2 * BB * QSTR + 2 * NC * 33) * (int)sizeof(float2);
    cudaFuncSetAttribute(rnn_layer, cudaFuncAttributeMaxDynamicSharedMemorySize, smem_bytes);

    float* h0all; cudaGetSymbolAddress((void**)&h0all, g_h0all);

    // 5 pad launches so ncu (-s 5 -c 1) captures rnn_layer (launch #6)
    init_kernel<<<1, 1>>>();
    nop_kernel<<<1, 1>>>();
    nop_kernel<<<1, 1>>>();
    nop_kernel<<<1, 1>>>();
    nop_kernel<<<1, 1>>>();
    // layer 0: x native [B][S][D] -> h0all [S][B][D]
    rnn_layer<<<NBLK, NTHR, smem_bytes>>>(
        x, (size_t)DD, (size_t)SS * DD,
        wh, uh, bias,
        h0all, (size_t)BB * DD, (size_t)DD, 0);
    // layer 1: h0all [S][B][D] -> out native [B][S][D]
    rnn_layer<<<NBLK, NTHR, smem_bytes>>>(
        h0all, (size_t)BB * DD, (size_t)DD,
        wh + DD * DD, uh + DD * DD, bias + DD,
        out, (size_t)DD, (size_t)SS * DD, 1);
}

// round 17
// speedup vs baseline: 2.6471x; 1.4954x over previous
#include <cuda_runtime.h>
#include <math.h>
#include <stdint.h>

#define DD 1024
#define BB 32
#define SS 512
#define NC 16            // columns per block
#define GRP 64           // blocks per layer group
#define NBLK 128         // 2 groups
#define NTHR 256         // 8 warps = 4 col-quads x 2 k-halves
#define QSTR 130         // phase-panel row stride (float2): 128 + 2 pad
#define WUSTR 1026       // weight row stride (float2)
#define KPH 128          // k per phase
#define NPH 4            // phases per 512-half

__device__ float g_h0all[(size_t)SS * BB * DD];  // layer-0 out, [S][B][D]
__device__ float g_hA[2][BB * DD];               // layer-0 recurrent state
__device__ float g_hB[2][BB * DD];               // layer-1 recurrent state
__device__ unsigned g_done[2];

__device__ __forceinline__ unsigned ld_acq(const unsigned* p) {
    unsigned v;
    asm volatile("ld.acquire.gpu.global.u32 %0, [%1];" : "=r"(v) : "l"(p) : "memory");
    return v;
}
__device__ __forceinline__ void red_release_add(unsigned* p) {
    asm volatile("red.release.gpu.global.add.u32 [%0], %1;" :: "l"(p), "r"(1u) : "memory");
}

__device__ __forceinline__ void fma2(unsigned long long& acc, unsigned long long a,
                                     unsigned long long b) {
    asm("fma.rn.f32x2 %0, %1, %2, %0;" : "+l"(acc) : "l"(a), "l"(b));
}

// XLA EmitFastTanh (with_fma): clamp 7.99881172180175781, fma Horner  [bit-exact]
__device__ __forceinline__ float xla_tanh_fma(float x) {
    const float kMax = 7.99881172180175781f;
    float tc = fmaxf(fminf(x, kMax), -kMax);
    float x2 = __fmul_rn(tc, tc);
    float p;
    p = fmaf(x2, -2.76076847742355e-16f, 2.00018790482477e-13f);
    p = fmaf(x2, p, -8.60467152213735e-11f);
    p = fmaf(x2, p,  5.12229709037114e-08f);
    p = fmaf(x2, p,  1.48572235717979e-05f);
    p = fmaf(x2, p,  6.37261928875436e-04f);
    p = fmaf(x2, p,  4.89352455891786e-03f);
    p = __fmul_rn(tc, p);
    float q;
    q = fmaf(x2, 1.19825839466702e-06f, 1.18534705686654e-04f);
    q = fmaf(x2, q, 2.26843463243900e-03f);
    q = fmaf(x2, q, 4.89352518554385e-03f);
    float r = __fdiv_rn(p, q);
    return (fabsf(x) < 0.0004f) ? x : r;
}

__global__ void init_kernel() { g_done[0] = 0u; g_done[1] = 0u; }
__global__ void nop_kernel() {}

// Fused 2-layer pipelined RNN. Blocks [0,64) = layer 0, [64,128) = layer 1.
// Layer 1 step t additionally waits for layer 0 to finish step t (h0all[t]).
// Warp w: col-quad cq=w>>1 (4 cols), k-half kh=w&1; 512-chain carried across 4 phases.
__global__ void __launch_bounds__(NTHR, 1) rnn_fused(
    const float* __restrict__ x,
    const float* __restrict__ wh,
    const float* __restrict__ uh,
    const float* __restrict__ bias,
    float* __restrict__ out)
{
    extern __shared__ float smem[];
    float2* wu2  = (float2*)smem;                 // [16][WUSTR]
    float2* q0   = wu2 + NC * WUSTR;              // [32][QSTR] kh=0 phase panel
    float2* q1   = q0 + BB * QSTR;                // [32][QSTR] kh=1 phase panel
    float2* red2 = q1 + BB * QSTR;                // [2][16][33]

    const int layer = blockIdx.x >> 6;
    const int gb    = blockIdx.x & 63;
    const int nb    = gb * NC;
    const int tid   = threadIdx.x;

    float* h0all; { h0all = g_h0all; }

    // per-layer bindings
    const float* in      = layer ? h0all : x;
    const size_t in_st_t = layer ? (size_t)BB * DD : (size_t)DD;
    const size_t in_st_b = layer ? (size_t)DD : (size_t)SS * DD;
    const float* W       = wh + (size_t)layer * DD * DD;
    const float* U       = uh + (size_t)layer * DD * DD;
    const float* bias_l  = bias + layer * DD;
    float* outp          = layer ? out : h0all;
    const size_t out_st_t = layer ? (size_t)DD : (size_t)BB * DD;
    const size_t out_st_b = layer ? (size_t)SS * DD : (size_t)DD;
    float* hst0 = layer ? g_hB[0] : g_hA[0];
    float* hst1 = layer ? g_hB[1] : g_hA[1];
    unsigned* ctrS = &g_done[layer];
    unsigned* ctrD = &g_done[0];      // dependency counter (used by layer 1)

    // interleaved weights (once): wu2[c][k] = (W[k][nb+c], U[k][nb+c])
    for (int i = tid; i < NC * DD; i += NTHR) {
        int c = i >> 10, k = i & 1023;
        wu2[c * WUSTR + k] = make_float2(W[(size_t)k * DD + nb + c],
                                         U[(size_t)k * DD + nb + c]);
    }
    // h_{-1} = 0 in slot 1 (step 0 reads slot (0+1)&1); 512 entries, 2/thread
    for (int i = tid; i < NC * BB; i += NTHR) {
        int b = i & 31, c = i >> 5;
        hst1[b * DD + nb + c] = 0.f;
    }
    __syncthreads();
    if (tid == 0) red_release_add(ctrS);

    const int w    = tid >> 5;
    const int lane = tid & 31;           // batch
    const int cq   = w >> 1;
    const int kh   = w & 1;
    const float bva = bias_l[nb + (tid >> 5)];
    const float bvb = bias_l[nb + (tid >> 5) + 8];

    const float2* myq = (kh ? q1 : q0) + lane * QSTR;
    const float2* wb0 = wu2 + (4 * cq + 0) * WUSTR + kh * 512;
    const float2* wb1 = wu2 + (4 * cq + 1) * WUSTR + kh * 512;
    const float2* wb2 = wu2 + (4 * cq + 2) * WUSTR + kh * 512;
    const float2* wb3 = wu2 + (4 * cq + 3) * WUSTR + kh * 512;

    for (int t = 0; t < SS; ++t) {
        // lockstep wait(s)
        if (tid == 0) {
            const unsigned tgtS = 64u * (unsigned)(t + 1);
            while (ld_acq(ctrS) < tgtS) { }
            if (layer) {
                const unsigned tgtD = 64u * (unsigned)(t + 2);   // layer0 done step t
                while (ld_acq(ctrD) < tgtD) { }
            }
        }
        __syncthreads();

        const float* xin = in + (size_t)t * in_st_t;
        const float* hin = (((t + 1) & 1) ? hst1 : hst0);

        unsigned long long acc0 = 0ull, acc1 = 0ull, acc2 = 0ull, acc3 = 0ull;
#pragma unroll
        for (int p = 0; p < NPH; ++p) {
            // ---- stage phase panels: q0: k in [p*128,+128); q1: +512 ----
            for (int i = tid; i < 2048; i += NTHR) {
                int qq = i >> 10, b = (i >> 5) & 31, g = i & 31;
                int koff = qq * 512 + p * KPH + 4 * g;
                float4 xv = __ldcg((const float4*)(xin + (size_t)b * in_st_b + koff));
                float4 hv = __ldcg((const float4*)(hin + (size_t)b * DD + koff));
                float2* dst = (qq ? q1 : q0) + b * QSTR + 4 * g;
                *(float4*)(dst)     = make_float4(xv.x, hv.x, xv.y, hv.y);
                *(float4*)(dst + 2) = make_float4(xv.z, hv.z, xv.w, hv.w);
            }
            __syncthreads();

            // ---- chains over this 128-k chunk (ascending k, acc carried) ----
            const ulonglong2* xh = (const ulonglong2*)(myq);          // offset 0 (R15 fix)
            const ulonglong2* w0 = (const ulonglong2*)(wb0 + p * KPH);
            const ulonglong2* w1 = (const ulonglong2*)(wb1 + p * KPH);
            const ulonglong2* w2 = (const ulonglong2*)(wb2 + p * KPH);
            const ulonglong2* w3 = (const ulonglong2*)(wb3 + p * KPH);
#pragma unroll 4
            for (int j = 0; j < KPH / 2; ++j) {
                const ulonglong2 a = xh[j];
                const ulonglong2 u0 = w0[j];
                const ulonglong2 u1 = w1[j];
                fma2(acc0, a.x, u0.x);
                fma2(acc1, a.x, u1.x);
                fma2(acc0, a.y, u0.y);
                fma2(acc1, a.y, u1.y);
                const ulonglong2 u2 = w2[j];
                const ulonglong2 u3 = w3[j];
                fma2(acc2, a.x, u2.x);
                fma2(acc3, a.x, u3.x);
                fma2(acc2, a.y, u2.y);
                fma2(acc3, a.y, u3.y);
            }
            __syncthreads();   // chunk consumed before next staging
        }

        // ---- exchange halves: red2[(kh*16 + col)*33 + b] = (ax_half, ah_half) ----
        {
            const int l0 = 4 * cq;
            *(unsigned long long*)&red2[(kh * 16 + l0 + 0) * 33 + lane] = acc0;
            *(unsigned long long*)&red2[(kh * 16 + l0 + 1) * 33 + lane] = acc1;
            *(unsigned long long*)&red2[(kh * 16 + l0 + 2) * 33 + lane] = acc2;
            *(unsigned long long*)&red2[(kh * 16 + l0 + 3) * 33 + lane] = acc3;
        }
        __syncthreads();

        // ---- join (kc=512), bias, tanh, publish: thread -> (b2, c2) and (b2, c2+8) ----
        {
            const int b2 = tid & 31, c2 = tid >> 5;
            float* hcur = ((t & 1) ? hst1 : hst0);

            const float2 f0 = red2[c2 * 33 + b2];
            const float2 f1 = red2[(16 + c2) * 33 + b2];
            const float ax = __fadd_rn(f0.x, f1.x);
            const float ah = __fadd_rn(f0.y, f1.y);
            const float v  = xla_tanh_fma(__fadd_rn(__fadd_rn(ax, ah), bva));
            hcur[b2 * DD + nb + c2] = v;
            outp[(size_t)t * out_st_t + (size_t)b2 * out_st_b + nb + c2] = v;

            const float2 g0 = red2[(c2 + 8) * 33 + b2];
            const float2 g1 = red2[(16 + c2 + 8) * 33 + b2];
            const float ax2 = __fadd_rn(g0.x, g1.x);
            const float ah2 = __fadd_rn(g0.y, g1.y);
            const float v2  = xla_tanh_fma(__fadd_rn(__fadd_rn(ax2, ah2), bvb));
            hcur[b2 * DD + nb + c2 + 8] = v2;
            outp[(size_t)t * out_st_t + (size_t)b2 * out_st_b + nb + c2 + 8] = v2;
        }
        __syncthreads();
        if (tid == 0) red_release_add(ctrS);   // release orders h/out stores
    }
}

extern "C" void kernel_launch(void* const* d_in, const int* in_sizes, int n_in,
                              void* d_out, int out_size) {
    const float* x    = (const float*)d_in[0];   // [32,512,1024]
    const float* wh   = (const float*)d_in[1];   // [2,1024,1024]
    const float* uh   = (const float*)d_in[2];   // [2,1024,1024]
    const float* bias = (const float*)d_in[3];   // [2,1024]
    float* out = (float*)d_out;                  // [32,512,1024]

    const int smem_bytes = (NC * WUSTR + 2 * BB * QSTR + 2 * NC * 33) * (int)sizeof(float2);
    cudaFuncSetAttribute(rnn_fused, cudaFuncAttributeMaxDynamicSharedMemorySize, smem_bytes);

    // hot kernel as the 5th launch (observed: ncu captures launch #5)
    init_kernel<<<1, 1>>>();
    nop_kernel<<<1, 1>>>();
    nop_kernel<<<1, 1>>>();
    nop_kernel<<<1, 1>>>();
    rnn_fused<<<NBLK, NTHR, smem_bytes>>>(x, wh, uh, bias, out);
}